// round 6
// baseline (speedup 1.0000x reference)
#include <cuda_runtime.h>
#include <cuda_bf16.h>
#include <math.h>
#include <stdint.h>

#define NB 8
#define NC 512
#define NL 1024
#define NH 8
#define DH 64
#define WIN 4
#define NT 9   // 2*WIN+1

// Scratch (allocation-free contract).
__device__ __nv_bfloat16 g_qh[NB * NC * NL];
__device__ __nv_bfloat16 g_ql[NB * NC * NL];
__device__ __nv_bfloat16 g_kh[NB * NC * NL];
__device__ __nv_bfloat16 g_kl[NB * NC * NL];
__device__ __nv_bfloat16 g_vh[NB * NC * NL];
__device__ __nv_bfloat16 g_vl[NB * NC * NL];
__device__ __nv_bfloat16 g_xT_hi[NB * NL * NC];
__device__ __nv_bfloat16 g_xT_lo[NB * NL * NC];
__device__ __nv_bfloat16 g_tT_hi[NB * NL * NC];
__device__ __nv_bfloat16 g_tT_lo[NB * NL * NC];
__device__ __nv_bfloat16 g_W_hi[4 * NC * NC];     // Wq*0.125, Wk, Wv, Wo
__device__ __nv_bfloat16 g_W_lo[4 * NC * NC];

// ---------------- PTX helpers (sm_80-portable only) ----------------
__device__ __forceinline__ void cp16(uint32_t dst, const void* src) {
    asm volatile("cp.async.cg.shared.global [%0], [%1], 16;" :: "r"(dst), "l"(src));
}
__device__ __forceinline__ void cp_commit() { asm volatile("cp.async.commit_group;"); }
__device__ __forceinline__ void cp_wait0() { asm volatile("cp.async.wait_group 0;" ::: "memory"); }
__device__ __forceinline__ void cp_wait1() { asm volatile("cp.async.wait_group 1;" ::: "memory"); }

__device__ __forceinline__ uint32_t smem_u32(const void* p) {
    uint32_t a;
    asm("{ .reg .u64 t; cvta.to.shared.u64 t, %1; cvt.u32.u64 %0, t; }" : "=r"(a) : "l"(p));
    return a;
}
__device__ __forceinline__ void ld4(uint32_t* r, uint32_t addr) {
    asm volatile("ldmatrix.sync.aligned.m8n8.x4.shared.b16 {%0,%1,%2,%3}, [%4];"
                 : "=r"(r[0]), "=r"(r[1]), "=r"(r[2]), "=r"(r[3]) : "r"(addr));
}
__device__ __forceinline__ void ld4t(uint32_t* r, uint32_t addr) {
    asm volatile("ldmatrix.sync.aligned.m8n8.x4.trans.shared.b16 {%0,%1,%2,%3}, [%4];"
                 : "=r"(r[0]), "=r"(r[1]), "=r"(r[2]), "=r"(r[3]) : "r"(addr));
}
// NOTE: non-volatile — register constraints carry all dependencies; lets ptxas schedule.
__device__ __forceinline__ void mma_bf16(float* d, const uint32_t* a, const uint32_t* b) {
    asm("mma.sync.aligned.m16n8k16.row.col.f32.bf16.bf16.f32 "
        "{%0,%1,%2,%3}, {%4,%5,%6,%7}, {%8,%9}, {%0,%1,%2,%3};"
        : "+f"(d[0]), "+f"(d[1]), "+f"(d[2]), "+f"(d[3])
        : "r"(a[0]), "r"(a[1]), "r"(a[2]), "r"(a[3]), "r"(b[0]), "r"(b[1]));
}
__device__ __forceinline__ void split2(float v0, float v1, uint32_t& hi, uint32_t& lo) {
    __nv_bfloat16 h0 = __float2bfloat16(v0), h1 = __float2bfloat16(v1);
    __nv_bfloat162 hp; hp.x = h0; hp.y = h1;
    __nv_bfloat162 lp;
    lp.x = __float2bfloat16(v0 - __bfloat162float(h0));
    lp.y = __float2bfloat16(v1 - __bfloat162float(h1));
    hi = *(uint32_t*)&hp; lo = *(uint32_t*)&lp;
}

// ---------------------------------------------------------------------------
// Prep kernels.
// ---------------------------------------------------------------------------
__global__ void split_w(const float* __restrict__ w0, const float* __restrict__ w1,
                        const float* __restrict__ w2, const float* __restrict__ w3)
{
    int widx = blockIdx.y;
    const float* w = widx == 0 ? w0 : widx == 1 ? w1 : widx == 2 ? w2 : w3;
    float alpha = (widx == 0) ? 0.125f : 1.f;
    int e = blockIdx.x * 256 + threadIdx.x;
    float v = w[e] * alpha;
    __nv_bfloat16 hi = __float2bfloat16(v);
    g_W_hi[widx * NC * NC + e] = hi;
    g_W_lo[widx * NC * NC + e] = __float2bfloat16(v - __bfloat162float(hi));
}

__global__ __launch_bounds__(256) void split_xT(const float* __restrict__ x)
{
    __shared__ float tile[32][33];
    int b = blockIdx.z, c0 = blockIdx.y * 32, l0 = blockIdx.x * 32;
    const float* xb = x + ((size_t)b * NC + c0) * NL + l0;
    int tx = threadIdx.x & 31, ty = threadIdx.x >> 5;
#pragma unroll
    for (int i = 0; i < 4; i++)
        tile[ty + i * 8][tx] = xb[(size_t)(ty + i * 8) * NL + tx];
    __syncthreads();
    size_t ob = ((size_t)b * NL + l0) * NC + c0;
#pragma unroll
    for (int i = 0; i < 4; i++) {
        int r = ty + i * 8;
        float v = tile[tx][r];
        __nv_bfloat16 hi = __float2bfloat16(v);
        g_xT_hi[ob + (size_t)r * NC + tx] = hi;
        g_xT_lo[ob + (size_t)r * NC + tx] = __float2bfloat16(v - __bfloat162float(hi));
    }
}

// ---------------------------------------------------------------------------
// mma.sync bf16x2 GEMM core. Term-major MMA ordering (reuse distance 16).
// QKV=true: fused 3-matrix launch (blockIdx.y in [0,12)), bf16 hi/lo outputs.
// QKV=false: single Wo matrix, fp32 output.
// ---------------------------------------------------------------------------
#define KC 32
#define RS 40
#define MAT_B (128 * RS * 2)
#define BUF_B (4 * MAT_B)

template<bool QKV>
__global__ __launch_bounds__(256) void gemm_mma(
    const __nv_bfloat16* __restrict__ Whi, const __nv_bfloat16* __restrict__ Wlo,
    const __nv_bfloat16* __restrict__ Bhi, const __nv_bfloat16* __restrict__ Blo,
    const float* __restrict__ b0, const float* __restrict__ b1,
    const float* __restrict__ b2, float* __restrict__ Y)
{
    extern __shared__ __align__(128) char smem[];

    const int b  = blockIdx.z;
    int which = 0, m0;
    if (QKV) { which = blockIdx.y >> 2; m0 = (blockIdx.y & 3) * 128; }
    else     { m0 = blockIdx.y * 128; }
    const int n0 = blockIdx.x * 128;

    const __nv_bfloat16* Ahi = Whi + (size_t)which * NC * NC;
    const __nv_bfloat16* Alo = Wlo + (size_t)which * NC * NC;
    const float* bias = QKV ? (which == 0 ? b0 : which == 1 ? b1 : b2) : b0;
    const float balpha = (QKV && which == 0) ? 0.125f : 1.f;
    const __nv_bfloat16* Bhi_b = Bhi + (size_t)b * NL * NC;
    const __nv_bfloat16* Blo_b = Blo + (size_t)b * NL * NC;

    const int t = threadIdx.x;
    const int warp = t >> 5, lane = t & 31;
    const int wm = (warp >> 2) * 64;
    const int wn = (warp & 3) * 32;
    const uint32_t sbase = smem_u32(smem);

    const int a_lr = lane & 15;
    const int a_hc = (lane >> 4) * 8;
    const int b_nr = (lane & 7) + ((lane >> 4) << 3);
    const int b_kc = ((lane >> 3) & 1) * 8;

    auto load_chunk = [&](int buf, int k0) {
#pragma unroll
        for (int it = 0; it < 8; it++) {
            int u = t + it * 256;
            int mat = u >> 9, rem = u & 511;
            int row = rem >> 2, c16 = rem & 3;
            const __nv_bfloat16* src;
            if (mat == 0)      src = Ahi   + (size_t)(m0 + row) * NC + k0 + c16 * 8;
            else if (mat == 1) src = Alo   + (size_t)(m0 + row) * NC + k0 + c16 * 8;
            else if (mat == 2) src = Bhi_b + (size_t)(n0 + row) * NC + k0 + c16 * 8;
            else               src = Blo_b + (size_t)(n0 + row) * NC + k0 + c16 * 8;
            cp16(sbase + buf * BUF_B + mat * MAT_B + row * (RS * 2) + c16 * 16, src);
        }
        cp_commit();
    };

    float d[4][4][4];
#pragma unroll
    for (int mi = 0; mi < 4; mi++)
#pragma unroll
        for (int ni = 0; ni < 4; ni++)
#pragma unroll
            for (int q = 0; q < 4; q++) d[mi][ni][q] = 0.f;

    load_chunk(0, 0);

    for (int ch = 0; ch < NC / KC; ch++) {
        const int buf = ch & 1;
        if (ch + 1 < NC / KC) { load_chunk(buf ^ 1, (ch + 1) * KC); cp_wait1(); }
        else cp_wait0();
        __syncthreads();

        const uint32_t base = sbase + buf * BUF_B;
#pragma unroll
        for (int ks = 0; ks < 2; ks++) {
            const int kc = ks * 16;
            uint32_t ah[4][4], al[4][4], bh[4][2], bl[4][2];
#pragma unroll
            for (int mi = 0; mi < 4; mi++) {
                uint32_t r = (wm + mi * 16 + a_lr) * (RS * 2) + (kc + a_hc) * 2;
                ld4(ah[mi], base + r);
                ld4(al[mi], base + MAT_B + r);
            }
#pragma unroll
            for (int pi = 0; pi < 2; pi++) {
                uint32_t r = (wn + pi * 16 + b_nr) * (RS * 2) + (kc + b_kc) * 2;
                uint32_t tmp[4];
                ld4(tmp, base + 2 * MAT_B + r);
                bh[2 * pi][0] = tmp[0]; bh[2 * pi][1] = tmp[1];
                bh[2 * pi + 1][0] = tmp[2]; bh[2 * pi + 1][1] = tmp[3];
                ld4(tmp, base + 3 * MAT_B + r);
                bl[2 * pi][0] = tmp[0]; bl[2 * pi][1] = tmp[1];
                bl[2 * pi + 1][0] = tmp[2]; bl[2 * pi + 1][1] = tmp[3];
            }
            // term-major: reuse distance 16 per accumulator
#pragma unroll
            for (int mi = 0; mi < 4; mi++)
#pragma unroll
                for (int ni = 0; ni < 4; ni++) mma_bf16(d[mi][ni], ah[mi], bh[ni]);
#pragma unroll
            for (int mi = 0; mi < 4; mi++)
#pragma unroll
                for (int ni = 0; ni < 4; ni++) mma_bf16(d[mi][ni], ah[mi], bl[ni]);
#pragma unroll
            for (int mi = 0; mi < 4; mi++)
#pragma unroll
                for (int ni = 0; ni < 4; ni++) mma_bf16(d[mi][ni], al[mi], bh[ni]);
        }
        __syncthreads();
    }

    const int erow = lane >> 2, ecol = 2 * (lane & 3);
#pragma unroll
    for (int mi = 0; mi < 4; mi++) {
        int mA = m0 + wm + mi * 16 + erow;
        float bvA = __ldg(bias + mA) * balpha;
        float bvB = __ldg(bias + mA + 8) * balpha;
        if (QKV) {
            __nv_bfloat16* Yh = (which == 0 ? g_qh : which == 1 ? g_kh : g_vh);
            __nv_bfloat16* Yl = (which == 0 ? g_ql : which == 1 ? g_kl : g_vl);
            __nv_bfloat16* ohA = Yh + ((size_t)b * NC + mA) * NL + n0 + wn + ecol;
            __nv_bfloat16* olA = Yl + ((size_t)b * NC + mA) * NL + n0 + wn + ecol;
            __nv_bfloat16* ohB = ohA + 8 * NL;
            __nv_bfloat16* olB = olA + 8 * NL;
#pragma unroll
            for (int ni = 0; ni < 4; ni++) {
                uint32_t hA, lA, hB, lB;
                split2(d[mi][ni][0] + bvA, d[mi][ni][1] + bvA, hA, lA);
                split2(d[mi][ni][2] + bvB, d[mi][ni][3] + bvB, hB, lB);
                *(uint32_t*)(ohA + ni * 8) = hA; *(uint32_t*)(olA + ni * 8) = lA;
                *(uint32_t*)(ohB + ni * 8) = hB; *(uint32_t*)(olB + ni * 8) = lB;
            }
        } else {
            float* rowA = Y + (size_t)b * NC * NL + (size_t)mA * NL + n0 + wn + ecol;
            float* rowB = rowA + 8 * NL;
#pragma unroll
            for (int ni = 0; ni < 4; ni++) {
                *(float2*)(rowA + ni * 8) = make_float2(d[mi][ni][0] + bvA, d[mi][ni][1] + bvA);
                *(float2*)(rowB + ni * 8) = make_float2(d[mi][ni][2] + bvB, d[mi][ni][3] + bvB);
            }
        }
    }
}

// ---------------------------------------------------------------------------
// Tensor-core flash attention (term-major MMA ordering).
// ---------------------------------------------------------------------------
#define P72 72
#define TILB (64 * P72 * 2)
#define OQH 0
#define OQL (TILB)
#define OKH (2 * TILB)
#define OKL (4 * TILB)
#define OVH (6 * TILB)
#define OVL (8 * TILB)
#define OF32 (10 * TILB)
#define ATTN_SMEM (OF32 + 3 * 576 * 4)

__global__ __launch_bounds__(128, 2) void attn_tc(
    const float* __restrict__ erk, const float* __restrict__ erv)
{
    extern __shared__ __align__(128) char sm[];
    const uint32_t sb = smem_u32(sm);
    float* rqs  = (float*)(sm + OF32);
    float* arel = rqs + 576;
    float* ervs = arel + 576;

    const int bh = blockIdx.y, b = bh >> 3, h = bh & 7;
    const int i0 = blockIdx.x * 64;
    const size_t gb = ((size_t)b * NC + h * DH) * NL;
    const __nv_bfloat16* gq[2] = {g_qh + gb, g_ql + gb};
    const __nv_bfloat16* gkv[4] = {g_kh + gb, g_kl + gb, g_vh + gb, g_vl + gb};

    const int t = threadIdx.x, lane = t & 31, w = t >> 5;
    const int lr = lane >> 2, lc = 2 * (lane & 3);

    const int qrow = (lane & 7) + ((lane >> 4) & 1) * 8, qcol = ((lane >> 3) & 1) * 8;
    const int krow = (lane & 7) + ((lane >> 3) & 1) * 8, kcol = ((lane >> 4) & 1) * 8;
    const int vrow = (lane & 7) + ((lane >> 4) & 1) * 8, vcol = ((lane >> 3) & 1) * 8;

#pragma unroll
    for (int it = 0; it < 8; it++) {
        int e = t + it * 128;
        int mat = e >> 9, rem = e & 511, row = rem >> 3, c16 = rem & 7;
        cp16(sb + (mat ? OQL : OQH) + row * (P72 * 2) + c16 * 16,
             gq[mat] + (size_t)row * NL + i0 + c16 * 8);
    }
    cp_commit();

    auto issue_kv = [&](int buf, int j0g) {
#pragma unroll
        for (int it = 0; it < 16; it++) {
            int e = t + it * 128;
            int mat = e >> 9, rem = e & 511, row = rem >> 3, c16 = rem & 7;
            uint32_t off = (mat == 0 ? OKH : mat == 1 ? OKL : mat == 2 ? OVH : OVL);
            cp16(sb + off + buf * TILB + row * (P72 * 2) + c16 * 16,
                 gkv[mat] + (size_t)row * NL + j0g + c16 * 8);
        }
        cp_commit();
    };
    issue_kv(0, 0);

    for (int e = t; e < NT * DH; e += 128) ervs[e] = erv[e];

    cp_wait1();
    __syncthreads();

    {
        const __nv_bfloat16* qsh = (const __nv_bfloat16*)(sm + OQH);
        const __nv_bfloat16* qsl = (const __nv_bfloat16*)(sm + OQL);
        for (int e = t; e < 64 * NT; e += 128) {
            int r = e / NT, tt = e % NT;
            float s = 0.f;
#pragma unroll 16
            for (int d = 0; d < DH; d++)
                s = fmaf(__bfloat162float(qsh[d * P72 + r]) + __bfloat162float(qsl[d * P72 + r]),
                         erk[tt * DH + d], s);
            rqs[e] = s;
            arel[e] = 0.f;
        }
    }

    uint32_t qhf[4][4], qlf[4][4];
#pragma unroll
    for (int kc = 0; kc < 4; kc++) {
        uint32_t r = ((kc * 16 + qrow) * P72 + 16 * w + qcol) * 2;
        ld4t(qhf[kc], sb + OQH + r);
        ld4t(qlf[kc], sb + OQL + r);
    }
    __syncthreads();

    float m0 = -INFINITY, m1 = -INFINITY, l0 = 0.f, l1 = 0.f;
    float o[8][4];
#pragma unroll
    for (int sbk = 0; sbk < 8; sbk++)
#pragma unroll
        for (int q = 0; q < 4; q++) o[sbk][q] = 0.f;

    const int iloc0 = 16 * w + lr, iloc1 = iloc0 + 8;

    for (int jt = 0; jt < 16; jt++) {
        const int j0 = jt * 64;
        const int buf = jt & 1;
        const bool band = (j0 - i0 <= 64) && (i0 - j0 <= 64);

        __syncthreads();
        if (jt + 1 < 16) { issue_kv(buf ^ 1, j0 + 64); cp_wait1(); }
        else cp_wait0();
        __syncthreads();

        // ---- S = Q K^T (term-major, reuse distance 8) ----
        float s[8][4];
#pragma unroll
        for (int sbk = 0; sbk < 8; sbk++)
#pragma unroll
            for (int q = 0; q < 4; q++) s[sbk][q] = 0.f;

        const uint32_t kh_b = sb + OKH + buf * TILB, kl_b = sb + OKL + buf * TILB;
#pragma unroll
        for (int kc = 0; kc < 4; kc++) {
            uint32_t kh4[4][4], kl4[4][4];
#pragma unroll
            for (int nb = 0; nb < 4; nb++) {
                uint32_t r = ((kc * 16 + krow) * P72 + nb * 16 + kcol) * 2;
                ld4t(kh4[nb], kh_b + r);
                ld4t(kl4[nb], kl_b + r);
            }
#pragma unroll
            for (int nb = 0; nb < 4; nb++) {
                mma_bf16(s[2 * nb], qhf[kc], kh4[nb]);
                mma_bf16(s[2 * nb + 1], qhf[kc], kh4[nb] + 2);
            }
#pragma unroll
            for (int nb = 0; nb < 4; nb++) {
                mma_bf16(s[2 * nb], qhf[kc], kl4[nb]);
                mma_bf16(s[2 * nb + 1], qhf[kc], kl4[nb] + 2);
            }
#pragma unroll
            for (int nb = 0; nb < 4; nb++) {
                mma_bf16(s[2 * nb], qlf[kc], kh4[nb]);
                mma_bf16(s[2 * nb + 1], qlf[kc], kh4[nb] + 2);
            }
        }

        if (band) {
#pragma unroll
            for (int sbk = 0; sbk < 8; sbk++) {
                int jg = j0 + sbk * 8 + lc;
                int t00 = jg - (i0 + iloc0) + WIN;
                int t10 = jg - (i0 + iloc1) + WIN;
                if (t00 >= 0 && t00 < NT)     s[sbk][0] += rqs[iloc0 * NT + t00];
                if (t00 + 1 >= 0 && t00 + 1 < NT) s[sbk][1] += rqs[iloc0 * NT + t00 + 1];
                if (t10 >= 0 && t10 < NT)     s[sbk][2] += rqs[iloc1 * NT + t10];
                if (t10 + 1 >= 0 && t10 + 1 < NT) s[sbk][3] += rqs[iloc1 * NT + t10 + 1];
            }
        }

        float mx0 = -INFINITY, mx1 = -INFINITY;
#pragma unroll
        for (int sbk = 0; sbk < 8; sbk++) {
            mx0 = fmaxf(mx0, fmaxf(s[sbk][0], s[sbk][1]));
            mx1 = fmaxf(mx1, fmaxf(s[sbk][2], s[sbk][3]));
        }
        mx0 = fmaxf(mx0, __shfl_xor_sync(0xffffffffu, mx0, 1));
        mx0 = fmaxf(mx0, __shfl_xor_sync(0xffffffffu, mx0, 2));
        mx1 = fmaxf(mx1, __shfl_xor_sync(0xffffffffu, mx1, 1));
        mx1 = fmaxf(mx1, __shfl_xor_sync(0xffffffffu, mx1, 2));
        float mn0 = fmaxf(m0, mx0), mn1 = fmaxf(m1, mx1);
        float f0 = __expf(m0 - mn0), f1 = __expf(m1 - mn1);
        float rs0 = 0.f, rs1 = 0.f;
#pragma unroll
        for (int sbk = 0; sbk < 8; sbk++) {
            s[sbk][0] = __expf(s[sbk][0] - mn0); rs0 += s[sbk][0];
            s[sbk][1] = __expf(s[sbk][1] - mn0); rs0 += s[sbk][1];
            s[sbk][2] = __expf(s[sbk][2] - mn1); rs1 += s[sbk][2];
            s[sbk][3] = __expf(s[sbk][3] - mn1); rs1 += s[sbk][3];
        }
        rs0 += __shfl_xor_sync(0xffffffffu, rs0, 1);
        rs0 += __shfl_xor_sync(0xffffffffu, rs0, 2);
        rs1 += __shfl_xor_sync(0xffffffffu, rs1, 1);
        rs1 += __shfl_xor_sync(0xffffffffu, rs1, 2);
        l0 = l0 * f0 + rs0; m0 = mn0;
        l1 = l1 * f1 + rs1; m1 = mn1;
#pragma unroll
        for (int sbk = 0; sbk < 8; sbk++) {
            o[sbk][0] *= f0; o[sbk][1] *= f0; o[sbk][2] *= f1; o[sbk][3] *= f1;
        }

        if ((lane & 3) == 0) {
#pragma unroll
            for (int tt = 0; tt < NT; tt++) {
                arel[iloc0 * NT + tt] *= f0;
                arel[iloc1 * NT + tt] *= f1;
            }
        }
        __syncwarp();
        if (band) {
#pragma unroll
            for (int sbk = 0; sbk < 8; sbk++) {
                int jg = j0 + sbk * 8 + lc;
                int t00 = jg - (i0 + iloc0) + WIN;
                int t10 = jg - (i0 + iloc1) + WIN;
                if (t00 >= 0 && t00 < NT)     arel[iloc0 * NT + t00]     += s[sbk][0];
                if (t00 + 1 >= 0 && t00 + 1 < NT) arel[iloc0 * NT + t00 + 1] += s[sbk][1];
                if (t10 >= 0 && t10 < NT)     arel[iloc1 * NT + t10]     += s[sbk][2];
                if (t10 + 1 >= 0 && t10 + 1 < NT) arel[iloc1 * NT + t10 + 1] += s[sbk][3];
            }
            __syncwarp();
        }

        uint32_t pha[4][4], pla[4][4];
#pragma unroll
        for (int kc = 0; kc < 4; kc++) {
            split2(s[2 * kc][0],     s[2 * kc][1],     pha[kc][0], pla[kc][0]);
            split2(s[2 * kc][2],     s[2 * kc][3],     pha[kc][1], pla[kc][1]);
            split2(s[2 * kc + 1][0], s[2 * kc + 1][1], pha[kc][2], pla[kc][2]);
            split2(s[2 * kc + 1][2], s[2 * kc + 1][3], pha[kc][3], pla[kc][3]);
        }

        // ---- O += P V (term-major) ----
        const uint32_t vh_b = sb + OVH + buf * TILB, vl_b = sb + OVL + buf * TILB;
#pragma unroll
        for (int kc = 0; kc < 4; kc++) {
            uint32_t vh4[4][4], vl4[4][4];
#pragma unroll
            for (int nb = 0; nb < 4; nb++) {
                uint32_t r = ((nb * 16 + vrow) * P72 + kc * 16 + vcol) * 2;
                ld4(vh4[nb], vh_b + r);
                ld4(vl4[nb], vl_b + r);
            }
#pragma unroll
            for (int nb = 0; nb < 4; nb++) {
                mma_bf16(o[2 * nb], pha[kc], vh4[nb]);
                mma_bf16(o[2 * nb + 1], pha[kc], vh4[nb] + 2);
            }
#pragma unroll
            for (int nb = 0; nb < 4; nb++) {
                mma_bf16(o[2 * nb], pha[kc], vl4[nb]);
                mma_bf16(o[2 * nb + 1], pha[kc], vl4[nb] + 2);
            }
#pragma unroll
            for (int nb = 0; nb < 4; nb++) {
                mma_bf16(o[2 * nb], pla[kc], vh4[nb]);
                mma_bf16(o[2 * nb + 1], pla[kc], vh4[nb] + 2);
            }
        }
    }

    float inv0 = 1.f / l0, inv1 = 1.f / l1;
    float ar0[NT], ar1[NT];
#pragma unroll
    for (int tt = 0; tt < NT; tt++) {
        ar0[tt] = arel[iloc0 * NT + tt];
        ar1[tt] = arel[iloc1 * NT + tt];
    }
    __nv_bfloat16* th0 = g_tT_hi + ((size_t)b * NL + i0 + iloc0) * NC + h * DH;
    __nv_bfloat16* tl0 = g_tT_lo + ((size_t)b * NL + i0 + iloc0) * NC + h * DH;
    __nv_bfloat16* th1 = th0 + (size_t)8 * NC;
    __nv_bfloat16* tl1 = tl0 + (size_t)8 * NC;
#pragma unroll
    for (int sbk = 0; sbk < 8; sbk++) {
        int d0 = sbk * 8 + lc;
        float r00 = 0.f, r01 = 0.f, r10 = 0.f, r11 = 0.f;
#pragma unroll
        for (int tt = 0; tt < NT; tt++) {
            float e0 = ervs[tt * DH + d0], e1 = ervs[tt * DH + d0 + 1];
            r00 = fmaf(ar0[tt], e0, r00); r01 = fmaf(ar0[tt], e1, r01);
            r10 = fmaf(ar1[tt], e0, r10); r11 = fmaf(ar1[tt], e1, r11);
        }
        uint32_t hA, lA, hB, lB;
        split2((o[sbk][0] + r00) * inv0, (o[sbk][1] + r01) * inv0, hA, lA);
        split2((o[sbk][2] + r10) * inv1, (o[sbk][3] + r11) * inv1, hB, lB);
        *(uint32_t*)(th0 + d0) = hA; *(uint32_t*)(tl0 + d0) = lA;
        *(uint32_t*)(th1 + d0) = hB; *(uint32_t*)(tl1 + d0) = lB;
    }
}

// ---------------------------------------------------------------------------
extern "C" void kernel_launch(void* const* d_in, const int* in_sizes, int n_in,
                              void* d_out, int out_size)
{
    const float* x   = (const float*)d_in[0];
    const float* Wq  = (const float*)d_in[1];
    const float* bq  = (const float*)d_in[2];
    const float* Wk  = (const float*)d_in[3];
    const float* bk  = (const float*)d_in[4];
    const float* Wv  = (const float*)d_in[5];
    const float* bv  = (const float*)d_in[6];
    const float* Wo  = (const float*)d_in[7];
    const float* bo  = (const float*)d_in[8];
    const float* erk = (const float*)d_in[9];
    const float* erv = (const float*)d_in[10];
    float* out = (float*)d_out;

    __nv_bfloat16 *xh, *xl, *th, *tl, *wh, *wl;
    cudaGetSymbolAddress((void**)&xh, g_xT_hi);
    cudaGetSymbolAddress((void**)&xl, g_xT_lo);
    cudaGetSymbolAddress((void**)&th, g_tT_hi);
    cudaGetSymbolAddress((void**)&tl, g_tT_lo);
    cudaGetSymbolAddress((void**)&wh, g_W_hi);
    cudaGetSymbolAddress((void**)&wl, g_W_lo);

    const int gemm_smem = 2 * BUF_B;
    cudaFuncSetAttribute(gemm_mma<true>,
                         cudaFuncAttributeMaxDynamicSharedMemorySize, gemm_smem);
    cudaFuncSetAttribute(gemm_mma<false>,
                         cudaFuncAttributeMaxDynamicSharedMemorySize, gemm_smem);
    cudaFuncSetAttribute(attn_tc,
                         cudaFuncAttributeMaxDynamicSharedMemorySize, ATTN_SMEM);

    split_w<<<dim3(NC * NC / 256, 4), 256>>>(Wq, Wk, Wv, Wo);
    split_xT<<<dim3(NL / 32, NC / 32, NB), 256>>>(x);

    const int WSZ = NC * NC;
    // Fused QKV projection: grid.y = 12 (3 matrices x 4 m-tiles)
    gemm_mma<true><<<dim3(NL / 128, 12, NB), 256, gemm_smem>>>(
        wh, wl, xh, xl, bq, bk, bv, nullptr);

    dim3 ga(NL / 64, NB * NH);
    attn_tc<<<ga, 128, ATTN_SMEM>>>(erk, erv);

    gemm_mma<false><<<dim3(NL / 128, 4, NB), 256, gemm_smem>>>(
        wh + 3 * WSZ, wl + 3 * WSZ, th, tl, bo, nullptr, nullptr, out);
}

// round 7
// speedup vs baseline: 1.0028x; 1.0028x over previous
#include <cuda_runtime.h>
#include <cuda_bf16.h>
#include <math.h>
#include <stdint.h>

#define NB 8
#define NC 512
#define NL 1024
#define NH 8
#define DH 64
#define WIN 4
#define NT 9   // 2*WIN+1

// Scratch (allocation-free contract).
__device__ __nv_bfloat16 g_qh[NB * NC * NL];
__device__ __nv_bfloat16 g_ql[NB * NC * NL];
__device__ __nv_bfloat16 g_kh[NB * NC * NL];
__device__ __nv_bfloat16 g_kl[NB * NC * NL];
__device__ __nv_bfloat16 g_vh[NB * NC * NL];
__device__ __nv_bfloat16 g_vl[NB * NC * NL];
__device__ __nv_bfloat16 g_xT_hi[NB * NL * NC];
__device__ __nv_bfloat16 g_xT_lo[NB * NL * NC];
__device__ __nv_bfloat16 g_tT_hi[NB * NL * NC];
__device__ __nv_bfloat16 g_tT_lo[NB * NL * NC];
__device__ __nv_bfloat16 g_W_hi[4 * NC * NC];     // Wq*0.125, Wk, Wv, Wo
__device__ __nv_bfloat16 g_W_lo[4 * NC * NC];

// ---------------- PTX helpers (sm_80-portable only) ----------------
__device__ __forceinline__ void cp16(uint32_t dst, const void* src) {
    asm volatile("cp.async.cg.shared.global [%0], [%1], 16;" :: "r"(dst), "l"(src));
}
__device__ __forceinline__ void cp_commit() { asm volatile("cp.async.commit_group;"); }
__device__ __forceinline__ void cp_wait0() { asm volatile("cp.async.wait_group 0;" ::: "memory"); }
__device__ __forceinline__ void cp_wait1() { asm volatile("cp.async.wait_group 1;" ::: "memory"); }

__device__ __forceinline__ uint32_t smem_u32(const void* p) {
    uint32_t a;
    asm("{ .reg .u64 t; cvta.to.shared.u64 t, %1; cvt.u32.u64 %0, t; }" : "=r"(a) : "l"(p));
    return a;
}
__device__ __forceinline__ void ld4(uint32_t* r, uint32_t addr) {
    asm volatile("ldmatrix.sync.aligned.m8n8.x4.shared.b16 {%0,%1,%2,%3}, [%4];"
                 : "=r"(r[0]), "=r"(r[1]), "=r"(r[2]), "=r"(r[3]) : "r"(addr));
}
__device__ __forceinline__ void ld4t(uint32_t* r, uint32_t addr) {
    asm volatile("ldmatrix.sync.aligned.m8n8.x4.trans.shared.b16 {%0,%1,%2,%3}, [%4];"
                 : "=r"(r[0]), "=r"(r[1]), "=r"(r[2]), "=r"(r[3]) : "r"(addr));
}
// NOTE: non-volatile — register constraints carry all dependencies; lets ptxas schedule.
__device__ __forceinline__ void mma_bf16(float* d, const uint32_t* a, const uint32_t* b) {
    asm("mma.sync.aligned.m16n8k16.row.col.f32.bf16.bf16.f32 "
        "{%0,%1,%2,%3}, {%4,%5,%6,%7}, {%8,%9}, {%0,%1,%2,%3};"
        : "+f"(d[0]), "+f"(d[1]), "+f"(d[2]), "+f"(d[3])
        : "r"(a[0]), "r"(a[1]), "r"(a[2]), "r"(a[3]), "r"(b[0]), "r"(b[1]));
}
__device__ __forceinline__ void split2(float v0, float v1, uint32_t& hi, uint32_t& lo) {
    __nv_bfloat16 h0 = __float2bfloat16(v0), h1 = __float2bfloat16(v1);
    __nv_bfloat162 hp; hp.x = h0; hp.y = h1;
    __nv_bfloat162 lp;
    lp.x = __float2bfloat16(v0 - __bfloat162float(h0));
    lp.y = __float2bfloat16(v1 - __bfloat162float(h1));
    hi = *(uint32_t*)&hp; lo = *(uint32_t*)&lp;
}

// ---------------------------------------------------------------------------
// Prep kernels.
// ---------------------------------------------------------------------------
__global__ void split_w(const float* __restrict__ w0, const float* __restrict__ w1,
                        const float* __restrict__ w2, const float* __restrict__ w3)
{
    int widx = blockIdx.y;
    const float* w = widx == 0 ? w0 : widx == 1 ? w1 : widx == 2 ? w2 : w3;
    float alpha = (widx == 0) ? 0.125f : 1.f;
    int e = blockIdx.x * 256 + threadIdx.x;
    float v = w[e] * alpha;
    __nv_bfloat16 hi = __float2bfloat16(v);
    g_W_hi[widx * NC * NC + e] = hi;
    g_W_lo[widx * NC * NC + e] = __float2bfloat16(v - __bfloat162float(hi));
}

__global__ __launch_bounds__(256) void split_xT(const float* __restrict__ x)
{
    __shared__ float tile[32][33];
    int b = blockIdx.z, c0 = blockIdx.y * 32, l0 = blockIdx.x * 32;
    const float* xb = x + ((size_t)b * NC + c0) * NL + l0;
    int tx = threadIdx.x & 31, ty = threadIdx.x >> 5;
#pragma unroll
    for (int i = 0; i < 4; i++)
        tile[ty + i * 8][tx] = xb[(size_t)(ty + i * 8) * NL + tx];
    __syncthreads();
    size_t ob = ((size_t)b * NL + l0) * NC + c0;
#pragma unroll
    for (int i = 0; i < 4; i++) {
        int r = ty + i * 8;
        float v = tile[tx][r];
        __nv_bfloat16 hi = __float2bfloat16(v);
        g_xT_hi[ob + (size_t)r * NC + tx] = hi;
        g_xT_lo[ob + (size_t)r * NC + tx] = __float2bfloat16(v - __bfloat162float(hi));
    }
}

// ---------------------------------------------------------------------------
// mma.sync bf16x2 GEMM core. Term-major MMA ordering (reuse distance 16).
// QKV=true: fused 3-matrix launch (blockIdx.y in [0,12)), bf16 hi/lo outputs.
// QKV=false: single Wo matrix, fp32 output.
// ---------------------------------------------------------------------------
#define KC 32
#define RS 40
#define MAT_B (128 * RS * 2)
#define BUF_B (4 * MAT_B)

template<bool QKV>
__global__ __launch_bounds__(256) void gemm_mma(
    const __nv_bfloat16* __restrict__ Whi, const __nv_bfloat16* __restrict__ Wlo,
    const __nv_bfloat16* __restrict__ Bhi, const __nv_bfloat16* __restrict__ Blo,
    const float* __restrict__ b0, const float* __restrict__ b1,
    const float* __restrict__ b2, float* __restrict__ Y)
{
    extern __shared__ __align__(128) char smem[];

    const int b  = blockIdx.z;
    int which = 0, m0;
    if (QKV) { which = blockIdx.y >> 2; m0 = (blockIdx.y & 3) * 128; }
    else     { m0 = blockIdx.y * 128; }
    const int n0 = blockIdx.x * 128;

    const __nv_bfloat16* Ahi = Whi + (size_t)which * NC * NC;
    const __nv_bfloat16* Alo = Wlo + (size_t)which * NC * NC;
    const float* bias = QKV ? (which == 0 ? b0 : which == 1 ? b1 : b2) : b0;
    const float balpha = (QKV && which == 0) ? 0.125f : 1.f;
    const __nv_bfloat16* Bhi_b = Bhi + (size_t)b * NL * NC;
    const __nv_bfloat16* Blo_b = Blo + (size_t)b * NL * NC;

    const int t = threadIdx.x;
    const int warp = t >> 5, lane = t & 31;
    const int wm = (warp >> 2) * 64;
    const int wn = (warp & 3) * 32;
    const uint32_t sbase = smem_u32(smem);

    const int a_lr = lane & 15;
    const int a_hc = (lane >> 4) * 8;
    const int b_nr = (lane & 7) + ((lane >> 4) << 3);
    const int b_kc = ((lane >> 3) & 1) * 8;

    auto load_chunk = [&](int buf, int k0) {
#pragma unroll
        for (int it = 0; it < 8; it++) {
            int u = t + it * 256;
            int mat = u >> 9, rem = u & 511;
            int row = rem >> 2, c16 = rem & 3;
            const __nv_bfloat16* src;
            if (mat == 0)      src = Ahi   + (size_t)(m0 + row) * NC + k0 + c16 * 8;
            else if (mat == 1) src = Alo   + (size_t)(m0 + row) * NC + k0 + c16 * 8;
            else if (mat == 2) src = Bhi_b + (size_t)(n0 + row) * NC + k0 + c16 * 8;
            else               src = Blo_b + (size_t)(n0 + row) * NC + k0 + c16 * 8;
            cp16(sbase + buf * BUF_B + mat * MAT_B + row * (RS * 2) + c16 * 16, src);
        }
        cp_commit();
    };

    float d[4][4][4];
#pragma unroll
    for (int mi = 0; mi < 4; mi++)
#pragma unroll
        for (int ni = 0; ni < 4; ni++)
#pragma unroll
            for (int q = 0; q < 4; q++) d[mi][ni][q] = 0.f;

    load_chunk(0, 0);

    for (int ch = 0; ch < NC / KC; ch++) {
        const int buf = ch & 1;
        if (ch + 1 < NC / KC) { load_chunk(buf ^ 1, (ch + 1) * KC); cp_wait1(); }
        else cp_wait0();
        __syncthreads();

        const uint32_t base = sbase + buf * BUF_B;
#pragma unroll
        for (int ks = 0; ks < 2; ks++) {
            const int kc = ks * 16;
            uint32_t ah[4][4], al[4][4], bh[4][2], bl[4][2];
#pragma unroll
            for (int mi = 0; mi < 4; mi++) {
                uint32_t r = (wm + mi * 16 + a_lr) * (RS * 2) + (kc + a_hc) * 2;
                ld4(ah[mi], base + r);
                ld4(al[mi], base + MAT_B + r);
            }
#pragma unroll
            for (int pi = 0; pi < 2; pi++) {
                uint32_t r = (wn + pi * 16 + b_nr) * (RS * 2) + (kc + b_kc) * 2;
                uint32_t tmp[4];
                ld4(tmp, base + 2 * MAT_B + r);
                bh[2 * pi][0] = tmp[0]; bh[2 * pi][1] = tmp[1];
                bh[2 * pi + 1][0] = tmp[2]; bh[2 * pi + 1][1] = tmp[3];
                ld4(tmp, base + 3 * MAT_B + r);
                bl[2 * pi][0] = tmp[0]; bl[2 * pi][1] = tmp[1];
                bl[2 * pi + 1][0] = tmp[2]; bl[2 * pi + 1][1] = tmp[3];
            }
            // term-major: reuse distance 16 per accumulator
#pragma unroll
            for (int mi = 0; mi < 4; mi++)
#pragma unroll
                for (int ni = 0; ni < 4; ni++) mma_bf16(d[mi][ni], ah[mi], bh[ni]);
#pragma unroll
            for (int mi = 0; mi < 4; mi++)
#pragma unroll
                for (int ni = 0; ni < 4; ni++) mma_bf16(d[mi][ni], ah[mi], bl[ni]);
#pragma unroll
            for (int mi = 0; mi < 4; mi++)
#pragma unroll
                for (int ni = 0; ni < 4; ni++) mma_bf16(d[mi][ni], al[mi], bh[ni]);
        }
        __syncthreads();
    }

    const int erow = lane >> 2, ecol = 2 * (lane & 3);
#pragma unroll
    for (int mi = 0; mi < 4; mi++) {
        int mA = m0 + wm + mi * 16 + erow;
        float bvA = __ldg(bias + mA) * balpha;
        float bvB = __ldg(bias + mA + 8) * balpha;
        if (QKV) {
            __nv_bfloat16* Yh = (which == 0 ? g_qh : which == 1 ? g_kh : g_vh);
            __nv_bfloat16* Yl = (which == 0 ? g_ql : which == 1 ? g_kl : g_vl);
            __nv_bfloat16* ohA = Yh + ((size_t)b * NC + mA) * NL + n0 + wn + ecol;
            __nv_bfloat16* olA = Yl + ((size_t)b * NC + mA) * NL + n0 + wn + ecol;
            __nv_bfloat16* ohB = ohA + 8 * NL;
            __nv_bfloat16* olB = olA + 8 * NL;
#pragma unroll
            for (int ni = 0; ni < 4; ni++) {
                uint32_t hA, lA, hB, lB;
                split2(d[mi][ni][0] + bvA, d[mi][ni][1] + bvA, hA, lA);
                split2(d[mi][ni][2] + bvB, d[mi][ni][3] + bvB, hB, lB);
                *(uint32_t*)(ohA + ni * 8) = hA; *(uint32_t*)(olA + ni * 8) = lA;
                *(uint32_t*)(ohB + ni * 8) = hB; *(uint32_t*)(olB + ni * 8) = lB;
            }
        } else {
            float* rowA = Y + (size_t)b * NC * NL + (size_t)mA * NL + n0 + wn + ecol;
            float* rowB = rowA + 8 * NL;
#pragma unroll
            for (int ni = 0; ni < 4; ni++) {
                *(float2*)(rowA + ni * 8) = make_float2(d[mi][ni][0] + bvA, d[mi][ni][1] + bvA);
                *(float2*)(rowB + ni * 8) = make_float2(d[mi][ni][2] + bvB, d[mi][ni][3] + bvB);
            }
        }
    }
}

// ---------------------------------------------------------------------------
// Tensor-core flash attention (term-major MMA ordering).
// ---------------------------------------------------------------------------
#define P72 72
#define TILB (64 * P72 * 2)
#define OQH 0
#define OQL (TILB)
#define OKH (2 * TILB)
#define OKL (4 * TILB)
#define OVH (6 * TILB)
#define OVL (8 * TILB)
#define OF32 (10 * TILB)
#define ATTN_SMEM (OF32 + 3 * 576 * 4)

__global__ __launch_bounds__(128, 2) void attn_tc(
    const float* __restrict__ erk, const float* __restrict__ erv)
{
    extern __shared__ __align__(128) char sm[];
    const uint32_t sb = smem_u32(sm);
    float* rqs  = (float*)(sm + OF32);
    float* arel = rqs + 576;
    float* ervs = arel + 576;

    const int bh = blockIdx.y, b = bh >> 3, h = bh & 7;
    const int i0 = blockIdx.x * 64;
    const size_t gb = ((size_t)b * NC + h * DH) * NL;
    const __nv_bfloat16* gq[2] = {g_qh + gb, g_ql + gb};
    const __nv_bfloat16* gkv[4] = {g_kh + gb, g_kl + gb, g_vh + gb, g_vl + gb};

    const int t = threadIdx.x, lane = t & 31, w = t >> 5;
    const int lr = lane >> 2, lc = 2 * (lane & 3);

    const int qrow = (lane & 7) + ((lane >> 4) & 1) * 8, qcol = ((lane >> 3) & 1) * 8;
    const int krow = (lane & 7) + ((lane >> 3) & 1) * 8, kcol = ((lane >> 4) & 1) * 8;
    const int vrow = (lane & 7) + ((lane >> 4) & 1) * 8, vcol = ((lane >> 3) & 1) * 8;

#pragma unroll
    for (int it = 0; it < 8; it++) {
        int e = t + it * 128;
        int mat = e >> 9, rem = e & 511, row = rem >> 3, c16 = rem & 7;
        cp16(sb + (mat ? OQL : OQH) + row * (P72 * 2) + c16 * 16,
             gq[mat] + (size_t)row * NL + i0 + c16 * 8);
    }
    cp_commit();

    auto issue_kv = [&](int buf, int j0g) {
#pragma unroll
        for (int it = 0; it < 16; it++) {
            int e = t + it * 128;
            int mat = e >> 9, rem = e & 511, row = rem >> 3, c16 = rem & 7;
            uint32_t off = (mat == 0 ? OKH : mat == 1 ? OKL : mat == 2 ? OVH : OVL);
            cp16(sb + off + buf * TILB + row * (P72 * 2) + c16 * 16,
                 gkv[mat] + (size_t)row * NL + j0g + c16 * 8);
        }
        cp_commit();
    };
    issue_kv(0, 0);

    for (int e = t; e < NT * DH; e += 128) ervs[e] = erv[e];

    cp_wait1();
    __syncthreads();

    {
        const __nv_bfloat16* qsh = (const __nv_bfloat16*)(sm + OQH);
        const __nv_bfloat16* qsl = (const __nv_bfloat16*)(sm + OQL);
        for (int e = t; e < 64 * NT; e += 128) {
            int r = e / NT, tt = e % NT;
            float s = 0.f;
#pragma unroll 16
            for (int d = 0; d < DH; d++)
                s = fmaf(__bfloat162float(qsh[d * P72 + r]) + __bfloat162float(qsl[d * P72 + r]),
                         erk[tt * DH + d], s);
            rqs[e] = s;
            arel[e] = 0.f;
        }
    }

    uint32_t qhf[4][4], qlf[4][4];
#pragma unroll
    for (int kc = 0; kc < 4; kc++) {
        uint32_t r = ((kc * 16 + qrow) * P72 + 16 * w + qcol) * 2;
        ld4t(qhf[kc], sb + OQH + r);
        ld4t(qlf[kc], sb + OQL + r);
    }
    __syncthreads();

    float m0 = -INFINITY, m1 = -INFINITY, l0 = 0.f, l1 = 0.f;
    float o[8][4];
#pragma unroll
    for (int sbk = 0; sbk < 8; sbk++)
#pragma unroll
        for (int q = 0; q < 4; q++) o[sbk][q] = 0.f;

    const int iloc0 = 16 * w + lr, iloc1 = iloc0 + 8;

    for (int jt = 0; jt < 16; jt++) {
        const int j0 = jt * 64;
        const int buf = jt & 1;
        const bool band = (j0 - i0 <= 64) && (i0 - j0 <= 64);

        __syncthreads();
        if (jt + 1 < 16) { issue_kv(buf ^ 1, j0 + 64); cp_wait1(); }
        else cp_wait0();
        __syncthreads();

        // ---- S = Q K^T (term-major, reuse distance 8) ----
        float s[8][4];
#pragma unroll
        for (int sbk = 0; sbk < 8; sbk++)
#pragma unroll
            for (int q = 0; q < 4; q++) s[sbk][q] = 0.f;

        const uint32_t kh_b = sb + OKH + buf * TILB, kl_b = sb + OKL + buf * TILB;
#pragma unroll
        for (int kc = 0; kc < 4; kc++) {
            uint32_t kh4[4][4], kl4[4][4];
#pragma unroll
            for (int nb = 0; nb < 4; nb++) {
                uint32_t r = ((kc * 16 + krow) * P72 + nb * 16 + kcol) * 2;
                ld4t(kh4[nb], kh_b + r);
                ld4t(kl4[nb], kl_b + r);
            }
#pragma unroll
            for (int nb = 0; nb < 4; nb++) {
                mma_bf16(s[2 * nb], qhf[kc], kh4[nb]);
                mma_bf16(s[2 * nb + 1], qhf[kc], kh4[nb] + 2);
            }
#pragma unroll
            for (int nb = 0; nb < 4; nb++) {
                mma_bf16(s[2 * nb], qhf[kc], kl4[nb]);
                mma_bf16(s[2 * nb + 1], qhf[kc], kl4[nb] + 2);
            }
#pragma unroll
            for (int nb = 0; nb < 4; nb++) {
                mma_bf16(s[2 * nb], qlf[kc], kh4[nb]);
                mma_bf16(s[2 * nb + 1], qlf[kc], kh4[nb] + 2);
            }
        }

        if (band) {
#pragma unroll
            for (int sbk = 0; sbk < 8; sbk++) {
                int jg = j0 + sbk * 8 + lc;
                int t00 = jg - (i0 + iloc0) + WIN;
                int t10 = jg - (i0 + iloc1) + WIN;
                if (t00 >= 0 && t00 < NT)     s[sbk][0] += rqs[iloc0 * NT + t00];
                if (t00 + 1 >= 0 && t00 + 1 < NT) s[sbk][1] += rqs[iloc0 * NT + t00 + 1];
                if (t10 >= 0 && t10 < NT)     s[sbk][2] += rqs[iloc1 * NT + t10];
                if (t10 + 1 >= 0 && t10 + 1 < NT) s[sbk][3] += rqs[iloc1 * NT + t10 + 1];
            }
        }

        float mx0 = -INFINITY, mx1 = -INFINITY;
#pragma unroll
        for (int sbk = 0; sbk < 8; sbk++) {
            mx0 = fmaxf(mx0, fmaxf(s[sbk][0], s[sbk][1]));
            mx1 = fmaxf(mx1, fmaxf(s[sbk][2], s[sbk][3]));
        }
        mx0 = fmaxf(mx0, __shfl_xor_sync(0xffffffffu, mx0, 1));
        mx0 = fmaxf(mx0, __shfl_xor_sync(0xffffffffu, mx0, 2));
        mx1 = fmaxf(mx1, __shfl_xor_sync(0xffffffffu, mx1, 1));
        mx1 = fmaxf(mx1, __shfl_xor_sync(0xffffffffu, mx1, 2));
        float mn0 = fmaxf(m0, mx0), mn1 = fmaxf(m1, mx1);
        float f0 = __expf(m0 - mn0), f1 = __expf(m1 - mn1);
        float rs0 = 0.f, rs1 = 0.f;
#pragma unroll
        for (int sbk = 0; sbk < 8; sbk++) {
            s[sbk][0] = __expf(s[sbk][0] - mn0); rs0 += s[sbk][0];
            s[sbk][1] = __expf(s[sbk][1] - mn0); rs0 += s[sbk][1];
            s[sbk][2] = __expf(s[sbk][2] - mn1); rs1 += s[sbk][2];
            s[sbk][3] = __expf(s[sbk][3] - mn1); rs1 += s[sbk][3];
        }
        rs0 += __shfl_xor_sync(0xffffffffu, rs0, 1);
        rs0 += __shfl_xor_sync(0xffffffffu, rs0, 2);
        rs1 += __shfl_xor_sync(0xffffffffu, rs1, 1);
        rs1 += __shfl_xor_sync(0xffffffffu, rs1, 2);
        l0 = l0 * f0 + rs0; m0 = mn0;
        l1 = l1 * f1 + rs1; m1 = mn1;
#pragma unroll
        for (int sbk = 0; sbk < 8; sbk++) {
            o[sbk][0] *= f0; o[sbk][1] *= f0; o[sbk][2] *= f1; o[sbk][3] *= f1;
        }

        if ((lane & 3) == 0) {
#pragma unroll
            for (int tt = 0; tt < NT; tt++) {
                arel[iloc0 * NT + tt] *= f0;
                arel[iloc1 * NT + tt] *= f1;
            }
        }
        __syncwarp();
        if (band) {
#pragma unroll
            for (int sbk = 0; sbk < 8; sbk++) {
                int jg = j0 + sbk * 8 + lc;
                int t00 = jg - (i0 + iloc0) + WIN;
                int t10 = jg - (i0 + iloc1) + WIN;
                if (t00 >= 0 && t00 < NT)     arel[iloc0 * NT + t00]     += s[sbk][0];
                if (t00 + 1 >= 0 && t00 + 1 < NT) arel[iloc0 * NT + t00 + 1] += s[sbk][1];
                if (t10 >= 0 && t10 < NT)     arel[iloc1 * NT + t10]     += s[sbk][2];
                if (t10 + 1 >= 0 && t10 + 1 < NT) arel[iloc1 * NT + t10 + 1] += s[sbk][3];
            }
            __syncwarp();
        }

        uint32_t pha[4][4], pla[4][4];
#pragma unroll
        for (int kc = 0; kc < 4; kc++) {
            split2(s[2 * kc][0],     s[2 * kc][1],     pha[kc][0], pla[kc][0]);
            split2(s[2 * kc][2],     s[2 * kc][3],     pha[kc][1], pla[kc][1]);
            split2(s[2 * kc + 1][0], s[2 * kc + 1][1], pha[kc][2], pla[kc][2]);
            split2(s[2 * kc + 1][2], s[2 * kc + 1][3], pha[kc][3], pla[kc][3]);
        }

        // ---- O += P V (term-major) ----
        const uint32_t vh_b = sb + OVH + buf * TILB, vl_b = sb + OVL + buf * TILB;
#pragma unroll
        for (int kc = 0; kc < 4; kc++) {
            uint32_t vh4[4][4], vl4[4][4];
#pragma unroll
            for (int nb = 0; nb < 4; nb++) {
                uint32_t r = ((nb * 16 + vrow) * P72 + kc * 16 + vcol) * 2;
                ld4(vh4[nb], vh_b + r);
                ld4(vl4[nb], vl_b + r);
            }
#pragma unroll
            for (int nb = 0; nb < 4; nb++) {
                mma_bf16(o[2 * nb], pha[kc], vh4[nb]);
                mma_bf16(o[2 * nb + 1], pha[kc], vh4[nb] + 2);
            }
#pragma unroll
            for (int nb = 0; nb < 4; nb++) {
                mma_bf16(o[2 * nb], pha[kc], vl4[nb]);
                mma_bf16(o[2 * nb + 1], pha[kc], vl4[nb] + 2);
            }
#pragma unroll
            for (int nb = 0; nb < 4; nb++) {
                mma_bf16(o[2 * nb], pla[kc], vh4[nb]);
                mma_bf16(o[2 * nb + 1], pla[kc], vh4[nb] + 2);
            }
        }
    }

    float inv0 = 1.f / l0, inv1 = 1.f / l1;
    float ar0[NT], ar1[NT];
#pragma unroll
    for (int tt = 0; tt < NT; tt++) {
        ar0[tt] = arel[iloc0 * NT + tt];
        ar1[tt] = arel[iloc1 * NT + tt];
    }
    __nv_bfloat16* th0 = g_tT_hi + ((size_t)b * NL + i0 + iloc0) * NC + h * DH;
    __nv_bfloat16* tl0 = g_tT_lo + ((size_t)b * NL + i0 + iloc0) * NC + h * DH;
    __nv_bfloat16* th1 = th0 + (size_t)8 * NC;
    __nv_bfloat16* tl1 = tl0 + (size_t)8 * NC;
#pragma unroll
    for (int sbk = 0; sbk < 8; sbk++) {
        int d0 = sbk * 8 + lc;
        float r00 = 0.f, r01 = 0.f, r10 = 0.f, r11 = 0.f;
#pragma unroll
        for (int tt = 0; tt < NT; tt++) {
            float e0 = ervs[tt * DH + d0], e1 = ervs[tt * DH + d0 + 1];
            r00 = fmaf(ar0[tt], e0, r00); r01 = fmaf(ar0[tt], e1, r01);
            r10 = fmaf(ar1[tt], e0, r10); r11 = fmaf(ar1[tt], e1, r11);
        }
        uint32_t hA, lA, hB, lB;
        split2((o[sbk][0] + r00) * inv0, (o[sbk][1] + r01) * inv0, hA, lA);
        split2((o[sbk][2] + r10) * inv1, (o[sbk][3] + r11) * inv1, hB, lB);
        *(uint32_t*)(th0 + d0) = hA; *(uint32_t*)(tl0 + d0) = lA;
        *(uint32_t*)(th1 + d0) = hB; *(uint32_t*)(tl1 + d0) = lB;
    }
}

// ---------------------------------------------------------------------------
extern "C" void kernel_launch(void* const* d_in, const int* in_sizes, int n_in,
                              void* d_out, int out_size)
{
    const float* x   = (const float*)d_in[0];
    const float* Wq  = (const float*)d_in[1];
    const float* bq  = (const float*)d_in[2];
    const float* Wk  = (const float*)d_in[3];
    const float* bk  = (const float*)d_in[4];
    const float* Wv  = (const float*)d_in[5];
    const float* bv  = (const float*)d_in[6];
    const float* Wo  = (const float*)d_in[7];
    const float* bo  = (const float*)d_in[8];
    const float* erk = (const float*)d_in[9];
    const float* erv = (const float*)d_in[10];
    float* out = (float*)d_out;

    __nv_bfloat16 *xh, *xl, *th, *tl, *wh, *wl;
    cudaGetSymbolAddress((void**)&xh, g_xT_hi);
    cudaGetSymbolAddress((void**)&xl, g_xT_lo);
    cudaGetSymbolAddress((void**)&th, g_tT_hi);
    cudaGetSymbolAddress((void**)&tl, g_tT_lo);
    cudaGetSymbolAddress((void**)&wh, g_W_hi);
    cudaGetSymbolAddress((void**)&wl, g_W_lo);

    const int gemm_smem = 2 * BUF_B;
    cudaFuncSetAttribute(gemm_mma<true>,
                         cudaFuncAttributeMaxDynamicSharedMemorySize, gemm_smem);
    cudaFuncSetAttribute(gemm_mma<false>,
                         cudaFuncAttributeMaxDynamicSharedMemorySize, gemm_smem);
    cudaFuncSetAttribute(attn_tc,
                         cudaFuncAttributeMaxDynamicSharedMemorySize, ATTN_SMEM);

    split_w<<<dim3(NC * NC / 256, 4), 256>>>(Wq, Wk, Wv, Wo);
    split_xT<<<dim3(NL / 32, NC / 32, NB), 256>>>(x);

    const int WSZ = NC * NC;
    // Fused QKV projection: grid.y = 12 (3 matrices x 4 m-tiles)
    gemm_mma<true><<<dim3(NL / 128, 12, NB), 256, gemm_smem>>>(
        wh, wl, xh, xl, bq, bk, bv, nullptr);

    dim3 ga(NL / 64, NB * NH);
    attn_tc<<<ga, 128, ATTN_SMEM>>>(erk, erv);

    gemm_mma<false><<<dim3(NL / 128, 4, NB), 256, gemm_smem>>>(
        wh + 3 * WSZ, wl + 3 * WSZ, th, tl, bo, nullptr, nullptr, out);
}

// round 8
// speedup vs baseline: 1.0122x; 1.0094x over previous
#include <cuda_runtime.h>
#include <cuda_bf16.h>
#include <math.h>
#include <stdint.h>

#define NB 8
#define NC 512
#define NL 1024
#define NH 8
#define DH 64
#define WIN 4
#define NT 9   // 2*WIN+1

// Scratch (allocation-free contract).
__device__ __nv_bfloat16 g_qh[NB * NC * NL];
__device__ __nv_bfloat16 g_ql[NB * NC * NL];
__device__ __nv_bfloat16 g_kh[NB * NC * NL];
__device__ __nv_bfloat16 g_kl[NB * NC * NL];
__device__ __nv_bfloat16 g_vh[NB * NC * NL];
__device__ __nv_bfloat16 g_vl[NB * NC * NL];
__device__ __nv_bfloat16 g_xT_hi[NB * NL * NC];
__device__ __nv_bfloat16 g_xT_lo[NB * NL * NC];
__device__ __nv_bfloat16 g_tT_hi[NB * NL * NC];
__device__ __nv_bfloat16 g_tT_lo[NB * NL * NC];
__device__ __nv_bfloat16 g_W_hi[4 * NC * NC];     // Wq*0.125, Wk, Wv, Wo
__device__ __nv_bfloat16 g_W_lo[4 * NC * NC];

// ---------------- PTX helpers (sm_80-portable only) ----------------
__device__ __forceinline__ void cp16(uint32_t dst, const void* src) {
    asm volatile("cp.async.cg.shared.global [%0], [%1], 16;" :: "r"(dst), "l"(src));
}
__device__ __forceinline__ void cp_commit() { asm volatile("cp.async.commit_group;"); }
__device__ __forceinline__ void cp_wait0() { asm volatile("cp.async.wait_group 0;" ::: "memory"); }
__device__ __forceinline__ void cp_wait1() { asm volatile("cp.async.wait_group 1;" ::: "memory"); }

__device__ __forceinline__ uint32_t smem_u32(const void* p) {
    uint32_t a;
    asm("{ .reg .u64 t; cvta.to.shared.u64 t, %1; cvt.u32.u64 %0, t; }" : "=r"(a) : "l"(p));
    return a;
}
__device__ __forceinline__ void ld4(uint32_t* r, uint32_t addr) {
    asm volatile("ldmatrix.sync.aligned.m8n8.x4.shared.b16 {%0,%1,%2,%3}, [%4];"
                 : "=r"(r[0]), "=r"(r[1]), "=r"(r[2]), "=r"(r[3]) : "r"(addr));
}
__device__ __forceinline__ void ld4t(uint32_t* r, uint32_t addr) {
    asm volatile("ldmatrix.sync.aligned.m8n8.x4.trans.shared.b16 {%0,%1,%2,%3}, [%4];"
                 : "=r"(r[0]), "=r"(r[1]), "=r"(r[2]), "=r"(r[3]) : "r"(addr));
}
__device__ __forceinline__ void mma_bf16(float* d, const uint32_t* a, const uint32_t* b) {
    asm("mma.sync.aligned.m16n8k16.row.col.f32.bf16.bf16.f32 "
        "{%0,%1,%2,%3}, {%4,%5,%6,%7}, {%8,%9}, {%0,%1,%2,%3};"
        : "+f"(d[0]), "+f"(d[1]), "+f"(d[2]), "+f"(d[3])
        : "r"(a[0]), "r"(a[1]), "r"(a[2]), "r"(a[3]), "r"(b[0]), "r"(b[1]));
}
__device__ __forceinline__ void split2(float v0, float v1, uint32_t& hi, uint32_t& lo) {
    __nv_bfloat16 h0 = __float2bfloat16(v0), h1 = __float2bfloat16(v1);
    __nv_bfloat162 hp; hp.x = h0; hp.y = h1;
    __nv_bfloat162 lp;
    lp.x = __float2bfloat16(v0 - __bfloat162float(h0));
    lp.y = __float2bfloat16(v1 - __bfloat162float(h1));
    hi = *(uint32_t*)&hp; lo = *(uint32_t*)&lp;
}

// ---------------------------------------------------------------------------
// Prep kernels.
// ---------------------------------------------------------------------------
__global__ void split_w(const float* __restrict__ w0, const float* __restrict__ w1,
                        const float* __restrict__ w2, const float* __restrict__ w3)
{
    int widx = blockIdx.y;
    const float* w = widx == 0 ? w0 : widx == 1 ? w1 : widx == 2 ? w2 : w3;
    float alpha = (widx == 0) ? 0.125f : 1.f;
    int e = blockIdx.x * 256 + threadIdx.x;
    float v = w[e] * alpha;
    __nv_bfloat16 hi = __float2bfloat16(v);
    g_W_hi[widx * NC * NC + e] = hi;
    g_W_lo[widx * NC * NC + e] = __float2bfloat16(v - __bfloat162float(hi));
}

__global__ __launch_bounds__(256) void split_xT(const float* __restrict__ x)
{
    __shared__ float tile[32][33];
    int b = blockIdx.z, c0 = blockIdx.y * 32, l0 = blockIdx.x * 32;
    const float* xb = x + ((size_t)b * NC + c0) * NL + l0;
    int tx = threadIdx.x & 31, ty = threadIdx.x >> 5;
#pragma unroll
    for (int i = 0; i < 4; i++)
        tile[ty + i * 8][tx] = xb[(size_t)(ty + i * 8) * NL + tx];
    __syncthreads();
    size_t ob = ((size_t)b * NL + l0) * NC + c0;
#pragma unroll
    for (int i = 0; i < 4; i++) {
        int r = ty + i * 8;
        float v = tile[tx][r];
        __nv_bfloat16 hi = __float2bfloat16(v);
        g_xT_hi[ob + (size_t)r * NC + tx] = hi;
        g_xT_lo[ob + (size_t)r * NC + tx] = __float2bfloat16(v - __bfloat162float(hi));
    }
}

// ---------------------------------------------------------------------------
// mma.sync bf16x2 GEMM (R5-measured inner ordering; fused QKV launch).
// ---------------------------------------------------------------------------
#define KC 32
#define RS 40
#define MAT_B (128 * RS * 2)
#define BUF_B (4 * MAT_B)

template<bool QKV>
__global__ __launch_bounds__(256) void gemm_mma(
    const __nv_bfloat16* __restrict__ Whi, const __nv_bfloat16* __restrict__ Wlo,
    const __nv_bfloat16* __restrict__ Bhi, const __nv_bfloat16* __restrict__ Blo,
    const float* __restrict__ b0, const float* __restrict__ b1,
    const float* __restrict__ b2, float* __restrict__ Y)
{
    extern __shared__ __align__(128) char smem[];

    const int b  = blockIdx.z;
    int which = 0, m0;
    if (QKV) { which = blockIdx.y >> 2; m0 = (blockIdx.y & 3) * 128; }
    else     { m0 = blockIdx.y * 128; }
    const int n0 = blockIdx.x * 128;

    const __nv_bfloat16* Ahi = Whi + (size_t)which * NC * NC;
    const __nv_bfloat16* Alo = Wlo + (size_t)which * NC * NC;
    const float* bias = QKV ? (which == 0 ? b0 : which == 1 ? b1 : b2) : b0;
    const float balpha = (QKV && which == 0) ? 0.125f : 1.f;
    const __nv_bfloat16* Bhi_b = Bhi + (size_t)b * NL * NC;
    const __nv_bfloat16* Blo_b = Blo + (size_t)b * NL * NC;

    const int t = threadIdx.x;
    const int warp = t >> 5, lane = t & 31;
    const int wm = (warp >> 2) * 64;
    const int wn = (warp & 3) * 32;
    const uint32_t sbase = smem_u32(smem);

    const int a_lr = lane & 15;
    const int a_hc = (lane >> 4) * 8;
    const int b_nr = (lane & 7) + ((lane >> 4) << 3);
    const int b_kc = ((lane >> 3) & 1) * 8;

    auto load_chunk = [&](int buf, int k0) {
#pragma unroll
        for (int it = 0; it < 8; it++) {
            int u = t + it * 256;
            int mat = u >> 9, rem = u & 511;
            int row = rem >> 2, c16 = rem & 3;
            const __nv_bfloat16* src;
            if (mat == 0)      src = Ahi   + (size_t)(m0 + row) * NC + k0 + c16 * 8;
            else if (mat == 1) src = Alo   + (size_t)(m0 + row) * NC + k0 + c16 * 8;
            else if (mat == 2) src = Bhi_b + (size_t)(n0 + row) * NC + k0 + c16 * 8;
            else               src = Blo_b + (size_t)(n0 + row) * NC + k0 + c16 * 8;
            cp16(sbase + buf * BUF_B + mat * MAT_B + row * (RS * 2) + c16 * 16, src);
        }
        cp_commit();
    };

    float d[4][4][4];
#pragma unroll
    for (int mi = 0; mi < 4; mi++)
#pragma unroll
        for (int ni = 0; ni < 4; ni++)
#pragma unroll
            for (int q = 0; q < 4; q++) d[mi][ni][q] = 0.f;

    load_chunk(0, 0);

    for (int ch = 0; ch < NC / KC; ch++) {
        const int buf = ch & 1;
        if (ch + 1 < NC / KC) { load_chunk(buf ^ 1, (ch + 1) * KC); cp_wait1(); }
        else cp_wait0();
        __syncthreads();

        const uint32_t base = sbase + buf * BUF_B;
#pragma unroll
        for (int ks = 0; ks < 2; ks++) {
            const int kc = ks * 16;
            uint32_t ah[4][4], al[4][4], bh[4][2], bl[4][2];
#pragma unroll
            for (int mi = 0; mi < 4; mi++) {
                uint32_t r = (wm + mi * 16 + a_lr) * (RS * 2) + (kc + a_hc) * 2;
                ld4(ah[mi], base + r);
                ld4(al[mi], base + MAT_B + r);
            }
#pragma unroll
            for (int pi = 0; pi < 2; pi++) {
                uint32_t r = (wn + pi * 16 + b_nr) * (RS * 2) + (kc + b_kc) * 2;
                uint32_t tmp[4];
                ld4(tmp, base + 2 * MAT_B + r);
                bh[2 * pi][0] = tmp[0]; bh[2 * pi][1] = tmp[1];
                bh[2 * pi + 1][0] = tmp[2]; bh[2 * pi + 1][1] = tmp[3];
                ld4(tmp, base + 3 * MAT_B + r);
                bl[2 * pi][0] = tmp[0]; bl[2 * pi][1] = tmp[1];
                bl[2 * pi + 1][0] = tmp[2]; bl[2 * pi + 1][1] = tmp[3];
            }
#pragma unroll
            for (int mi = 0; mi < 4; mi++)
#pragma unroll
                for (int ni = 0; ni < 4; ni++) {
                    mma_bf16(d[mi][ni], ah[mi], bh[ni]);
                    mma_bf16(d[mi][ni], ah[mi], bl[ni]);
                    mma_bf16(d[mi][ni], al[mi], bh[ni]);
                }
        }
        __syncthreads();
    }

    const int erow = lane >> 2, ecol = 2 * (lane & 3);
#pragma unroll
    for (int mi = 0; mi < 4; mi++) {
        int mA = m0 + wm + mi * 16 + erow;
        float bvA = __ldg(bias + mA) * balpha;
        float bvB = __ldg(bias + mA + 8) * balpha;
        if (QKV) {
            __nv_bfloat16* Yh = (which == 0 ? g_qh : which == 1 ? g_kh : g_vh);
            __nv_bfloat16* Yl = (which == 0 ? g_ql : which == 1 ? g_kl : g_vl);
            __nv_bfloat16* ohA = Yh + ((size_t)b * NC + mA) * NL + n0 + wn + ecol;
            __nv_bfloat16* olA = Yl + ((size_t)b * NC + mA) * NL + n0 + wn + ecol;
            __nv_bfloat16* ohB = ohA + 8 * NL;
            __nv_bfloat16* olB = olA + 8 * NL;
#pragma unroll
            for (int ni = 0; ni < 4; ni++) {
                uint32_t hA, lA, hB, lB;
                split2(d[mi][ni][0] + bvA, d[mi][ni][1] + bvA, hA, lA);
                split2(d[mi][ni][2] + bvB, d[mi][ni][3] + bvB, hB, lB);
                *(uint32_t*)(ohA + ni * 8) = hA; *(uint32_t*)(olA + ni * 8) = lA;
                *(uint32_t*)(ohB + ni * 8) = hB; *(uint32_t*)(olB + ni * 8) = lB;
            }
        } else {
            float* rowA = Y + (size_t)b * NC * NL + (size_t)mA * NL + n0 + wn + ecol;
            float* rowB = rowA + 8 * NL;
#pragma unroll
            for (int ni = 0; ni < 4; ni++) {
                *(float2*)(rowA + ni * 8) = make_float2(d[mi][ni][0] + bvA, d[mi][ni][1] + bvA);
                *(float2*)(rowB + ni * 8) = make_float2(d[mi][ni][2] + bvB, d[mi][ni][3] + bvB);
            }
        }
    }
}

// ---------------------------------------------------------------------------
// Tensor-core flash attention. K double-buffered; V single-buffered aliased
// onto the (dead-after-prologue) Q region. Smem 62208 B -> 3 CTAs/SM.
// ---------------------------------------------------------------------------
#define P72 72
#define TILB (64 * P72 * 2)      // 9216
#define OK 0                     // K: buf b at b*2*TILB, [Khi, Klo]
#define OQ (4 * TILB)            // 36864: Q hi/lo in prologue, then V hi/lo
#define OV OQ
#define OF32 (6 * TILB)          // 55296
#define ATTN_SMEM (OF32 + 3 * 576 * 4)   // 62208

__global__ __launch_bounds__(128, 3) void attn_tc(
    const float* __restrict__ erk, const float* __restrict__ erv)
{
    extern __shared__ __align__(128) char sm[];
    const uint32_t sb = smem_u32(sm);
    float* rqs  = (float*)(sm + OF32);
    float* arel = rqs + 576;
    float* ervs = arel + 576;

    const int bh = blockIdx.y, b = bh >> 3, h = bh & 7;
    const int i0 = blockIdx.x * 64;
    const size_t gb = ((size_t)b * NC + h * DH) * NL;
    const __nv_bfloat16* gq[2] = {g_qh + gb, g_ql + gb};
    const __nv_bfloat16* gk[2] = {g_kh + gb, g_kl + gb};
    const __nv_bfloat16* gv[2] = {g_vh + gb, g_vl + gb};

    const int t = threadIdx.x, lane = t & 31, w = t >> 5;
    const int lr = lane >> 2, lc = 2 * (lane & 3);

    const int qrow = (lane & 7) + ((lane >> 4) & 1) * 8, qcol = ((lane >> 3) & 1) * 8;
    const int krow = (lane & 7) + ((lane >> 3) & 1) * 8, kcol = ((lane >> 4) & 1) * 8;
    const int vrow = (lane & 7) + ((lane >> 4) & 1) * 8, vcol = ((lane >> 3) & 1) * 8;

    // issue helpers: 2 tiles (hi/lo) = 1024 x 16B chunks, 8 iters @128 thr
    auto issue_k = [&](int buf, int j0g) {
#pragma unroll
        for (int it = 0; it < 8; it++) {
            int e = t + it * 128;
            int mat = e >> 9, rem = e & 511, row = rem >> 3, c16 = rem & 7;
            cp16(sb + OK + buf * 2 * TILB + mat * TILB + row * (P72 * 2) + c16 * 16,
                 gk[mat] + (size_t)row * NL + j0g + c16 * 8);
        }
        cp_commit();
    };
    auto issue_v = [&](int j0g) {
#pragma unroll
        for (int it = 0; it < 8; it++) {
            int e = t + it * 128;
            int mat = e >> 9, rem = e & 511, row = rem >> 3, c16 = rem & 7;
            cp16(sb + OV + mat * TILB + row * (P72 * 2) + c16 * 16,
                 gv[mat] + (size_t)row * NL + j0g + c16 * 8);
        }
        cp_commit();
    };

    // Prologue: Q -> OQ (group 1), K0 -> Kbuf0 (group 2)
#pragma unroll
    for (int it = 0; it < 8; it++) {
        int e = t + it * 128;
        int mat = e >> 9, rem = e & 511, row = rem >> 3, c16 = rem & 7;
        cp16(sb + OQ + mat * TILB + row * (P72 * 2) + c16 * 16,
             gq[mat] + (size_t)row * NL + i0 + c16 * 8);
    }
    cp_commit();
    issue_k(0, 0);

    for (int e = t; e < NT * DH; e += 128) ervs[e] = erv[e];

    cp_wait1();          // Q done (K0 may pend)
    __syncthreads();

    // rq from Q smem; arel = 0
    {
        const __nv_bfloat16* qsh = (const __nv_bfloat16*)(sm + OQ);
        const __nv_bfloat16* qsl = (const __nv_bfloat16*)(sm + OQ + TILB);
        for (int e = t; e < 64 * NT; e += 128) {
            int r = e / NT, tt = e % NT;
            float s = 0.f;
#pragma unroll 16
            for (int d = 0; d < DH; d++)
                s = fmaf(__bfloat162float(qsh[d * P72 + r]) + __bfloat162float(qsl[d * P72 + r]),
                         erk[tt * DH + d], s);
            rqs[e] = s;
            arel[e] = 0.f;
        }
    }

    // Q fragments (persistent in registers)
    uint32_t qhf[4][4], qlf[4][4];
#pragma unroll
    for (int kc = 0; kc < 4; kc++) {
        uint32_t r = ((kc * 16 + qrow) * P72 + 16 * w + qcol) * 2;
        ld4t(qhf[kc], sb + OQ + r);
        ld4t(qlf[kc], sb + OQ + TILB + r);
    }
    __syncthreads();     // everyone done with the Q region

    // V0 overwrites Q region (group 3); K1 -> Kbuf1 (group 4)
    issue_v(0);
    issue_k(1, 64);

    float m0 = -INFINITY, m1 = -INFINITY, l0 = 0.f, l1 = 0.f;
    float o[8][4];
#pragma unroll
    for (int sbk = 0; sbk < 8; sbk++)
#pragma unroll
        for (int q = 0; q < 4; q++) o[sbk][q] = 0.f;

    const int iloc0 = 16 * w + lr, iloc1 = iloc0 + 8;

    for (int jt = 0; jt < 16; jt++) {
        const int j0 = jt * 64;
        const int buf = jt & 1;
        const bool band = (j0 - i0 <= 64) && (i0 - j0 <= 64);

        // wait: all groups except the newest (K(jt+1)) complete -> V(jt), K(jt) ready
        if (jt < 15) cp_wait1(); else cp_wait0();
        __syncthreads();

        // ---- S = Q K^T (R5 ordering) ----
        float s[8][4];
#pragma unroll
        for (int sbk = 0; sbk < 8; sbk++)
#pragma unroll
            for (int q = 0; q < 4; q++) s[sbk][q] = 0.f;

        const uint32_t kh_b = sb + OK + buf * 2 * TILB, kl_b = kh_b + TILB;
#pragma unroll
        for (int nb = 0; nb < 4; nb++) {
#pragma unroll
            for (int kc = 0; kc < 4; kc++) {
                uint32_t r = ((kc * 16 + krow) * P72 + nb * 16 + kcol) * 2;
                uint32_t kh4[4], kl4[4];
                ld4t(kh4, kh_b + r);
                ld4t(kl4, kl_b + r);
                mma_bf16(s[2 * nb],     qhf[kc], kh4);
                mma_bf16(s[2 * nb],     qhf[kc], kl4);
                mma_bf16(s[2 * nb],     qlf[kc], kh4);
                mma_bf16(s[2 * nb + 1], qhf[kc], kh4 + 2);
                mma_bf16(s[2 * nb + 1], qhf[kc], kl4 + 2);
                mma_bf16(s[2 * nb + 1], qlf[kc], kh4 + 2);
            }
        }

        if (band) {
#pragma unroll
            for (int sbk = 0; sbk < 8; sbk++) {
                int jg = j0 + sbk * 8 + lc;
                int t00 = jg - (i0 + iloc0) + WIN;
                int t10 = jg - (i0 + iloc1) + WIN;
                if (t00 >= 0 && t00 < NT)     s[sbk][0] += rqs[iloc0 * NT + t00];
                if (t00 + 1 >= 0 && t00 + 1 < NT) s[sbk][1] += rqs[iloc0 * NT + t00 + 1];
                if (t10 >= 0 && t10 < NT)     s[sbk][2] += rqs[iloc1 * NT + t10];
                if (t10 + 1 >= 0 && t10 + 1 < NT) s[sbk][3] += rqs[iloc1 * NT + t10 + 1];
            }
        }

        // ---- online softmax ----
        float mx0 = -INFINITY, mx1 = -INFINITY;
#pragma unroll
        for (int sbk = 0; sbk < 8; sbk++) {
            mx0 = fmaxf(mx0, fmaxf(s[sbk][0], s[sbk][1]));
            mx1 = fmaxf(mx1, fmaxf(s[sbk][2], s[sbk][3]));
        }
        mx0 = fmaxf(mx0, __shfl_xor_sync(0xffffffffu, mx0, 1));
        mx0 = fmaxf(mx0, __shfl_xor_sync(0xffffffffu, mx0, 2));
        mx1 = fmaxf(mx1, __shfl_xor_sync(0xffffffffu, mx1, 1));
        mx1 = fmaxf(mx1, __shfl_xor_sync(0xffffffffu, mx1, 2));
        float mn0 = fmaxf(m0, mx0), mn1 = fmaxf(m1, mx1);
        float f0 = __expf(m0 - mn0), f1 = __expf(m1 - mn1);
        float rs0 = 0.f, rs1 = 0.f;
#pragma unroll
        for (int sbk = 0; sbk < 8; sbk++) {
            s[sbk][0] = __expf(s[sbk][0] - mn0); rs0 += s[sbk][0];
            s[sbk][1] = __expf(s[sbk][1] - mn0); rs0 += s[sbk][1];
            s[sbk][2] = __expf(s[sbk][2] - mn1); rs1 += s[sbk][2];
            s[sbk][3] = __expf(s[sbk][3] - mn1); rs1 += s[sbk][3];
        }
        rs0 += __shfl_xor_sync(0xffffffffu, rs0, 1);
        rs0 += __shfl_xor_sync(0xffffffffu, rs0, 2);
        rs1 += __shfl_xor_sync(0xffffffffu, rs1, 1);
        rs1 += __shfl_xor_sync(0xffffffffu, rs1, 2);
        l0 = l0 * f0 + rs0; m0 = mn0;
        l1 = l1 * f1 + rs1; m1 = mn1;
#pragma unroll
        for (int sbk = 0; sbk < 8; sbk++) {
            o[sbk][0] *= f0; o[sbk][1] *= f0; o[sbk][2] *= f1; o[sbk][3] *= f1;
        }

        if ((lane & 3) == 0) {
#pragma unroll
            for (int tt = 0; tt < NT; tt++) {
                arel[iloc0 * NT + tt] *= f0;
                arel[iloc1 * NT + tt] *= f1;
            }
        }
        __syncwarp();
        if (band) {
#pragma unroll
            for (int sbk = 0; sbk < 8; sbk++) {
                int jg = j0 + sbk * 8 + lc;
                int t00 = jg - (i0 + iloc0) + WIN;
                int t10 = jg - (i0 + iloc1) + WIN;
                if (t00 >= 0 && t00 < NT)     arel[iloc0 * NT + t00]     += s[sbk][0];
                if (t00 + 1 >= 0 && t00 + 1 < NT) arel[iloc0 * NT + t00 + 1] += s[sbk][1];
                if (t10 >= 0 && t10 < NT)     arel[iloc1 * NT + t10]     += s[sbk][2];
                if (t10 + 1 >= 0 && t10 + 1 < NT) arel[iloc1 * NT + t10 + 1] += s[sbk][3];
            }
            __syncwarp();
        }

        // ---- pack P (hi/lo) ----
        uint32_t pha[4][4], pla[4][4];
#pragma unroll
        for (int kc = 0; kc < 4; kc++) {
            split2(s[2 * kc][0],     s[2 * kc][1],     pha[kc][0], pla[kc][0]);
            split2(s[2 * kc][2],     s[2 * kc][3],     pha[kc][1], pla[kc][1]);
            split2(s[2 * kc + 1][0], s[2 * kc + 1][1], pha[kc][2], pla[kc][2]);
            split2(s[2 * kc + 1][2], s[2 * kc + 1][3], pha[kc][3], pla[kc][3]);
        }

        // ---- O += P V (R5 ordering) ----
        const uint32_t vh_b = sb + OV, vl_b = sb + OV + TILB;
#pragma unroll
        for (int nb = 0; nb < 4; nb++) {
#pragma unroll
            for (int kc = 0; kc < 4; kc++) {
                uint32_t r = ((nb * 16 + vrow) * P72 + kc * 16 + vcol) * 2;
                uint32_t vh4[4], vl4[4];
                ld4(vh4, vh_b + r);
                ld4(vl4, vl_b + r);
                mma_bf16(o[2 * nb],     pha[kc], vh4);
                mma_bf16(o[2 * nb],     pha[kc], vl4);
                mma_bf16(o[2 * nb],     pla[kc], vh4);
                mma_bf16(o[2 * nb + 1], pha[kc], vh4 + 2);
                mma_bf16(o[2 * nb + 1], pha[kc], vl4 + 2);
                mma_bf16(o[2 * nb + 1], pla[kc], vh4 + 2);
            }
        }

        __syncthreads();   // all warps done reading V and Kbuf[jt&1]
        if (jt + 1 < 16) issue_v(j0 + 64);
        if (jt + 2 < 16) issue_k(buf, j0 + 128);
    }

    // ---- epilogue ----
    float inv0 = 1.f / l0, inv1 = 1.f / l1;
    float ar0[NT], ar1[NT];
#pragma unroll
    for (int tt = 0; tt < NT; tt++) {
        ar0[tt] = arel[iloc0 * NT + tt];
        ar1[tt] = arel[iloc1 * NT + tt];
    }
    __nv_bfloat16* th0 = g_tT_hi + ((size_t)b * NL + i0 + iloc0) * NC + h * DH;
    __nv_bfloat16* tl0 = g_tT_lo + ((size_t)b * NL + i0 + iloc0) * NC + h * DH;
    __nv_bfloat16* th1 = th0 + (size_t)8 * NC;
    __nv_bfloat16* tl1 = tl0 + (size_t)8 * NC;
#pragma unroll
    for (int sbk = 0; sbk < 8; sbk++) {
        int d0 = sbk * 8 + lc;
        float r00 = 0.f, r01 = 0.f, r10 = 0.f, r11 = 0.f;
#pragma unroll
        for (int tt = 0; tt < NT; tt++) {
            float e0 = ervs[tt * DH + d0], e1 = ervs[tt * DH + d0 + 1];
            r00 = fmaf(ar0[tt], e0, r00); r01 = fmaf(ar0[tt], e1, r01);
            r10 = fmaf(ar1[tt], e0, r10); r11 = fmaf(ar1[tt], e1, r11);
        }
        uint32_t hA, lA, hB, lB;
        split2((o[sbk][0] + r00) * inv0, (o[sbk][1] + r01) * inv0, hA, lA);
        split2((o[sbk][2] + r10) * inv1, (o[sbk][3] + r11) * inv1, hB, lB);
        *(uint32_t*)(th0 + d0) = hA; *(uint32_t*)(tl0 + d0) = lA;
        *(uint32_t*)(th1 + d0) = hB; *(uint32_t*)(tl1 + d0) = lB;
    }
}

// ---------------------------------------------------------------------------
extern "C" void kernel_launch(void* const* d_in, const int* in_sizes, int n_in,
                              void* d_out, int out_size)
{
    const float* x   = (const float*)d_in[0];
    const float* Wq  = (const float*)d_in[1];
    const float* bq  = (const float*)d_in[2];
    const float* Wk  = (const float*)d_in[3];
    const float* bk  = (const float*)d_in[4];
    const float* Wv  = (const float*)d_in[5];
    const float* bv  = (const float*)d_in[6];
    const float* Wo  = (const float*)d_in[7];
    const float* bo  = (const float*)d_in[8];
    const float* erk = (const float*)d_in[9];
    const float* erv = (const float*)d_in[10];
    float* out = (float*)d_out;

    __nv_bfloat16 *xh, *xl, *th, *tl, *wh, *wl;
    cudaGetSymbolAddress((void**)&xh, g_xT_hi);
    cudaGetSymbolAddress((void**)&xl, g_xT_lo);
    cudaGetSymbolAddress((void**)&th, g_tT_hi);
    cudaGetSymbolAddress((void**)&tl, g_tT_lo);
    cudaGetSymbolAddress((void**)&wh, g_W_hi);
    cudaGetSymbolAddress((void**)&wl, g_W_lo);

    const int gemm_smem = 2 * BUF_B;
    cudaFuncSetAttribute(gemm_mma<true>,
                         cudaFuncAttributeMaxDynamicSharedMemorySize, gemm_smem);
    cudaFuncSetAttribute(gemm_mma<false>,
                         cudaFuncAttributeMaxDynamicSharedMemorySize, gemm_smem);
    cudaFuncSetAttribute(attn_tc,
                         cudaFuncAttributeMaxDynamicSharedMemorySize, ATTN_SMEM);

    split_w<<<dim3(NC * NC / 256, 4), 256>>>(Wq, Wk, Wv, Wo);
    split_xT<<<dim3(NL / 32, NC / 32, NB), 256>>>(x);

    const int WSZ = NC * NC;
    gemm_mma<true><<<dim3(NL / 128, 12, NB), 256, gemm_smem>>>(
        wh, wl, xh, xl, bq, bk, bv, nullptr);

    dim3 ga(NL / 64, NB * NH);
    attn_tc<<<ga, 128, ATTN_SMEM>>>(erk, erv);

    gemm_mma<false><<<dim3(NL / 128, 4, NB), 256, gemm_smem>>>(
        wh + 3 * WSZ, wl + 3 * WSZ, th, tl, bo, nullptr, nullptr, out);
}